// round 12
// baseline (speedup 1.0000x reference)
#include <cuda_runtime.h>
#include <cstdint>

#define BB   512      // batch
#define LL   512      // leaves
#define EE   128      // emb
#define OPS  5
#define NI   511      // internal nodes
#define RPC  4        // batch rows per CTA

typedef unsigned long long ull;

// scratch: all node embeddings [B][NI][E]  (~134 MB)
__device__ float g_nodes[(size_t)BB * NI * EE];

// ---------------- packed f32x2 helpers ----------------
__device__ __forceinline__ ull pack2(float lo, float hi) {
    ull r;
    asm("mov.b64 %0, {%1, %2};" : "=l"(r) : "f"(lo), "f"(hi));
    return r;
}
__device__ __forceinline__ void fma2(ull& d, ull a, ull b) {
    asm("fma.rn.f32x2 %0, %1, %2, %0;" : "+l"(d) : "l"(a), "l"(b));
}
__device__ __forceinline__ ull add2(ull a, ull b) {
    ull r;
    asm("add.rn.f32x2 %0, %1, %2;" : "=l"(r) : "l"(a), "l"(b));
    return r;
}
__device__ __forceinline__ float2 unpack2(ull v) {
    float2 f;
    asm("mov.b64 {%0, %1}, %2;" : "=f"(f.x), "=f"(f.y) : "l"(v));
    return f;
}

// dynamic-smem layout for the recurrence kernel
struct RecurSmem {
    float cur[2][RPC][EE];     // double-buffered state (4 KB)
    float leafs[2][RPC][EE];   // double-buffered right leaf (4 KB)
    float red[32][RPC][EE];    // per-warp partials (64 KB)
    int   ridx[NI + 1];
};

// ---------------- sequential recurrence ----------------
// Warp-sliced broadcast layout at 1024 threads = 32 warps (8 warps/SMSP).
// Warp w owns the 8-float K-slice [8w..8w+7] of the 256-float concat
// [cur | leaf] (warps 0-15: cur, 16-31: leaf; Ww row index is uniformly 8w).
// Lane l owns output cols {l, l+32, l+64, l+96}. All 32 lanes read the SAME
// 16B x-chunk -> broadcast = 1 L1 wavefront per LDS.128.
// Per thread-step: 8 LDS.128-bcast + 64 fma2 + 16 STS (phase A) and
// 16 coalesced LDS + shfl pair-combine (phase B). 2 barriers/step.
__global__ void __launch_bounds__(1024, 1) recur_kernel(
    const float* __restrict__ emb,   // [B, L, E]
    const float* __restrict__ Ww,    // [2E, E]
    const float* __restrict__ Wb,    // [E]
    const int*   __restrict__ li,    // [NI]
    const int*   __restrict__ ri)    // [NI]
{
    extern __shared__ char smem_raw[];
    RecurSmem* sm = (RecurSmem*)smem_raw;

    const int t    = threadIdx.x;
    const int wid  = t >> 5;        // warp = K-slice 0..31
    const int lane = t & 31;
    const int b0   = blockIdx.x * RPC;

    // Weight slice: Ww rows 8*wid..+7, cols lane+32c. 16 b64 = 32 regs.
    ull w[4][4];
#pragma unroll
    for (int c = 0; c < 4; c++) {
        const int n = lane + 32 * c;
#pragma unroll
        for (int i = 0; i < 4; i++) {
            const int k = 8 * wid + 2 * i;
            w[c][i] = pack2(Ww[(size_t)k * EE + n], Ww[(size_t)(k + 1) * EE + n]);
        }
    }
    // phase-B ownership: thread pair (t even/odd) handles output (rrow, rcol);
    // even sums slices 0-15, odd sums 16-31; even commits.
    const int   po    = t >> 1;           // 0..511
    const int   half  = t & 1;
    const int   rcol  = po & 127;
    const int   rrow  = po >> 7;          // 0..3
    const float biasv = Wb[rcol];
    const int   slbase = half * 16;

    // right-leaf indices into smem
    for (int j = t; j < NI; j += 1024) sm->ridx[j] = ri[j];
    if (t == 0) sm->ridx[NI] = ri[0];   // dummy for prefetch overrun

    // init cur[0] = leaf(left_idx[0]); loader: threads 0..511, 1 float each
    const int l0   = li[0];
    const int r_ld = (t >> 7) & 3;
    const int c_ld = t & 127;
    if (t < 512)
        sm->cur[0][r_ld][c_ld] = emb[((size_t)(b0 + r_ld) * LL + l0) * EE + c_ld];
    __syncthreads();

    // prefetch right leaf for step 0 (loader threads only)
    float lv = 0.f;
    if (t < 512)
        lv = emb[((size_t)(b0 + r_ld) * LL + sm->ridx[0]) * EE + c_ld];

    for (int j = 0; j < NI; j++) {
        const int rb   = j & 1;         // read state buffer
        const int wbuf = rb ^ 1;        // write state buffer
        // commit prefetched leaf; barrier 1 covers leaf + prev cur commits
        if (t < 512) sm->leafs[rb][r_ld][c_ld] = lv;
        const int rnext = sm->ridx[j + 1];
        __syncthreads();
        if (t < 512)
            lv = emb[((size_t)(b0 + r_ld) * LL + rnext) * EE + c_ld];

        // ---- phase A: per-warp 8-K-slice partials, broadcast x reads ----
#pragma unroll
        for (int r = 0; r < RPC; r++) {
            const ulonglong2* xs = (wid < 16)
                ? (const ulonglong2*)&sm->cur[rb][r][wid * 8]
                : (const ulonglong2*)&sm->leafs[rb][r][(wid - 16) * 8];
            ull a0[4] = {0ull, 0ull, 0ull, 0ull};
            ull a1[4] = {0ull, 0ull, 0ull, 0ull};
#pragma unroll
            for (int jj = 0; jj < 2; jj++) {
                const ulonglong2 p = xs[jj];        // broadcast: 1 wavefront
#pragma unroll
                for (int c = 0; c < 4; c++) {
                    fma2(a0[c], p.x, w[c][2*jj]);
                    fma2(a1[c], p.y, w[c][2*jj+1]);
                }
            }
#pragma unroll
            for (int c = 0; c < 4; c++) {
                const float2 f = unpack2(add2(a0[c], a1[c]));
                sm->red[wid][r][lane + 32 * c] = f.x + f.y;  // contiguous/warp
            }
        }
        __syncthreads();                 // barrier 2: partials ready

        // ---- phase B: pair-summed reduce, 1 commit per even thread ----
        {
            // tree-sum 16 slices (independent adds for ILP)
            float s0 = sm->red[slbase + 0][rrow][rcol] + sm->red[slbase + 1][rrow][rcol];
            float s1 = sm->red[slbase + 2][rrow][rcol] + sm->red[slbase + 3][rrow][rcol];
            float s2 = sm->red[slbase + 4][rrow][rcol] + sm->red[slbase + 5][rrow][rcol];
            float s3 = sm->red[slbase + 6][rrow][rcol] + sm->red[slbase + 7][rrow][rcol];
            float s4 = sm->red[slbase + 8][rrow][rcol] + sm->red[slbase + 9][rrow][rcol];
            float s5 = sm->red[slbase +10][rrow][rcol] + sm->red[slbase +11][rrow][rcol];
            float s6 = sm->red[slbase +12][rrow][rcol] + sm->red[slbase +13][rrow][rcol];
            float s7 = sm->red[slbase +14][rrow][rcol] + sm->red[slbase +15][rrow][rcol];
            float s = ((s0 + s1) + (s2 + s3)) + ((s4 + s5) + (s6 + s7));
            s += __shfl_xor_sync(0xFFFFFFFFu, s, 1);   // combine halves
            if (half == 0) {
                const float v = s + biasv;
                sm->cur[wbuf][rrow][rcol] = v;
                g_nodes[((size_t)(b0 + rrow) * NI + j) * EE + rcol] = v;
            }
        }
        // next iteration's barrier 1 orders cur[wbuf] commits vs reads
    }
}

// ---------------- parallel projection: op = node @ G_w + G_b ----------------
// 4 nodes per warp (4 outstanding LDG.128 -> DRAM latency shared)
__global__ void __launch_bounds__(256) proj_kernel(
    const float* __restrict__ Gw,   // [E, OPS]
    const float* __restrict__ Gb,   // [OPS]
    float* __restrict__ out,        // [B, NI, OPS]
    int total_quads)
{
    __shared__ float gws[EE * OPS];
    __shared__ float gbs[OPS];
    const int t = threadIdx.x;
    for (int i = t; i < EE * OPS; i += blockDim.x) gws[i] = Gw[i];
    if (t < OPS) gbs[t] = Gb[t];
    __syncthreads();

    const int quad = blockIdx.x * (blockDim.x >> 5) + (t >> 5);
    if (quad >= total_quads) return;
    const int lane  = t & 31;
    const size_t n0 = (size_t)quad * 4;

    float4 x[4];
#pragma unroll
    for (int q = 0; q < 4; q++)
        x[q] = *(const float4*)&g_nodes[(n0 + q) * EE + lane * 4];
    const float* g = &gws[lane * 4 * OPS];

    float p[4][OPS];
#pragma unroll
    for (int q = 0; q < 4; q++)
#pragma unroll
        for (int o = 0; o < OPS; o++)
            p[q][o] = x[q].x * g[o] + x[q].y * g[OPS + o]
                    + x[q].z * g[2 * OPS + o] + x[q].w * g[3 * OPS + o];

#pragma unroll
    for (int off = 16; off; off >>= 1)
#pragma unroll
        for (int q = 0; q < 4; q++)
#pragma unroll
            for (int o = 0; o < OPS; o++)
                p[q][o] += __shfl_xor_sync(0xFFFFFFFFu, p[q][o], off);

    if (lane == 0) {
        float* op = out + n0 * OPS;
#pragma unroll
        for (int q = 0; q < 4; q++)
#pragma unroll
            for (int o = 0; o < OPS; o++)
                op[q * OPS + o] = p[q][o] + gbs[o];
    }
}

// ---------------- labels tail ----------------
// Labels land on device as int32 (JAX x64 disabled). mode 1: float cast.
// mode 2: widen to raw int64.
__global__ void tail_kernel(const int* __restrict__ labels, float* __restrict__ out, int mode)
{
    const int j = blockIdx.x * blockDim.x + threadIdx.x;
    if (j >= NI) return;
    const size_t base = (size_t)BB * NI * OPS;
    if (mode == 1) {
        out[base + j] = (float)labels[j];
    } else {
        ((long long*)(out + base))[j] = (long long)labels[j];
    }
}

extern "C" void kernel_launch(void* const* d_in, const int* in_sizes, int n_in,
                              void* d_out, int out_size)
{
    const float* emb    = (const float*)d_in[0];
    const float* Ww     = (const float*)d_in[1];
    const float* Wb     = (const float*)d_in[2];
    const float* Gw     = (const float*)d_in[3];
    const float* Gb     = (const float*)d_in[4];
    const int*   li     = (const int*)d_in[5];
    const int*   ri     = (const int*)d_in[6];
    const int*   labels = (const int*)d_in[7];
    float*       out    = (float*)d_out;

    const int smem_bytes = (int)sizeof(RecurSmem);
    cudaFuncSetAttribute(recur_kernel,
                         cudaFuncAttributeMaxDynamicSharedMemorySize, smem_bytes);

    recur_kernel<<<BB / RPC, 1024, smem_bytes>>>(emb, Ww, Wb, li, ri);

    const int total_quads = BB * NI / 4;                   // 65408
    proj_kernel<<<total_quads / 8, 256>>>(Gw, Gb, out, total_quads); // 8 warps/block

    const long long base = (long long)BB * NI * OPS;
    const long long tail = (long long)out_size - base;
    if (tail == NI)          tail_kernel<<<2, 256>>>(labels, out, 1);
    else if (tail == 2 * NI) tail_kernel<<<2, 256>>>(labels, out, 2);
}

// round 13
// speedup vs baseline: 1.4001x; 1.4001x over previous
#include <cuda_runtime.h>
#include <cstdint>

#define BB   512      // batch
#define LL   512      // leaves
#define EE   128      // emb
#define OPS  5
#define NI   511      // internal nodes
#define RPC  4        // batch rows per CTA

typedef unsigned long long ull;

// scratch: all node embeddings [B][NI][E]  (~134 MB)
__device__ float g_nodes[(size_t)BB * NI * EE];

// ---------------- packed f32x2 helpers ----------------
__device__ __forceinline__ ull pack2(float lo, float hi) {
    ull r;
    asm("mov.b64 %0, {%1, %2};" : "=l"(r) : "f"(lo), "f"(hi));
    return r;
}
__device__ __forceinline__ void fma2(ull& d, ull a, ull b) {
    asm("fma.rn.f32x2 %0, %1, %2, %0;" : "+l"(d) : "l"(a), "l"(b));
}
__device__ __forceinline__ ull add2(ull a, ull b) {
    ull r;
    asm("add.rn.f32x2 %0, %1, %2;" : "=l"(r) : "l"(a), "l"(b));
    return r;
}
__device__ __forceinline__ float2 unpack2(ull v) {
    float2 f;
    asm("mov.b64 {%0, %1}, %2;" : "=f"(f.x), "=f"(f.y) : "l"(v));
    return f;
}
__device__ __forceinline__ ull shfl_xor64(ull v, int m) {
    return __shfl_xor_sync(0xFFFFFFFFu, v, m);
}

// ---------------- sequential recurrence ----------------
// Warp-sliced broadcast layout, 512 threads = 16 warps (4 warps/SMSP).
// Warp w owns the 16-float K-slice [16w..16w+15] of the 256-float concat
// [cur | leaf] (warps 0-7: cur, 8-15: leaf). Lane l owns adjacent col pairs
// {2l, 2l+1} and {2l+64, 2l+65} so red writes/commits are packed 64-bit.
// Phase A: 16 LDS.128-bcast + 128 fma2 + 8 STS.64 per thread-step.
// Phase B: thread pairs split the 16 slices (8 LDS.64 each), add2 tree,
// 64-bit shuffle combine, even thread commits one col-pair. 2 barriers/step.
__global__ void __launch_bounds__(512, 1) recur_kernel(
    const float* __restrict__ emb,   // [B, L, E]
    const float* __restrict__ Ww,    // [2E, E]
    const float* __restrict__ Wb,    // [E]
    const int*   __restrict__ li,    // [NI]
    const int*   __restrict__ ri)    // [NI]
{
    __shared__ __align__(16) float cur[2][RPC][EE];    // double-buffered state
    __shared__ __align__(16) float leafs[2][RPC][EE];  // double-buffered right leaf
    __shared__ __align__(16) float red[16][RPC][EE];   // per-warp partials (32 KB)
    __shared__ int ridx[NI + 2];

    const int t    = threadIdx.x;
    const int wid  = t >> 5;        // warp = K-slice 0..15
    const int lane = t & 31;
    const int b0   = blockIdx.x * RPC;

    // cols owned by this lane (two adjacent pairs)
    const int nc[4] = { 2 * lane, 2 * lane + 1, 2 * lane + 64, 2 * lane + 65 };

    // Weight slice: Ww rows 16*wid..+15, 4 cols. 32 b64 regs.
    ull w[4][8];
#pragma unroll
    for (int c = 0; c < 4; c++) {
        const int n = nc[c];
#pragma unroll
        for (int i = 0; i < 8; i++) {
            const int k = 16 * wid + 2 * i;
            w[c][i] = pack2(Ww[(size_t)k * EE + n], Ww[(size_t)(k + 1) * EE + n]);
        }
    }
    // phase-B ownership: pair (t, t^1) handles output (rrow, col-pair pc);
    // half 0 sums slices 0-7, half 1 sums 8-15; half 0 commits.
    const int po   = t >> 1;            // 0..255
    const int half = t & 1;
    const int rrow = po >> 6;           // 0..3
    const int pc   = (po & 63) * 2;     // col-pair base 0,2,..,126
    const ull biasp = pack2(Wb[pc], Wb[pc + 1]);
    const int slb  = half * 8;

    // right-leaf indices into smem (+2 dummies for distance-2 prefetch)
    for (int j = t; j < NI; j += 512) ridx[j] = ri[j];
    if (t == 0) { ridx[NI] = ri[0]; ridx[NI + 1] = ri[0]; }

    // init cur[0] = leaf(left_idx[0]); loader: 4 rows x 128 cols, 1 float each
    const int l0   = li[0];
    const int r_ld = t >> 7;
    const int c_ld = t & 127;
    cur[0][r_ld][c_ld] = emb[((size_t)(b0 + r_ld) * LL + l0) * EE + c_ld];
    __syncthreads();

    // distance-2 leaf prefetch
    float lv0 = emb[((size_t)(b0 + r_ld) * LL + ridx[0]) * EE + c_ld];
    float lv1 = emb[((size_t)(b0 + r_ld) * LL + ridx[1]) * EE + c_ld];

    for (int j = 0; j < NI; j++) {
        const int rb   = j & 1;         // read state buffer
        const int wbuf = rb ^ 1;        // write state buffer
        // commit leaf for this step; barrier 1 covers leaf + prev cur commits
        leafs[rb][r_ld][c_ld] = lv0;
        const int rnext = ridx[j + 2];
        __syncthreads();
        lv0 = lv1;
        lv1 = emb[((size_t)(b0 + r_ld) * LL + rnext) * EE + c_ld];

        // ---- phase A: per-warp 16-K-slice partials, broadcast x reads ----
#pragma unroll
        for (int r = 0; r < RPC; r++) {
            const ulonglong2* xs = (wid < 8)
                ? (const ulonglong2*)&cur[rb][r][wid * 16]
                : (const ulonglong2*)&leafs[rb][r][(wid - 8) * 16];
            ull a0[4] = {0ull, 0ull, 0ull, 0ull};
            ull a1[4] = {0ull, 0ull, 0ull, 0ull};
#pragma unroll
            for (int jj = 0; jj < 4; jj++) {
                const ulonglong2 p = xs[jj];        // broadcast: 1 wavefront
#pragma unroll
                for (int c = 0; c < 4; c++) {
                    fma2(a0[c], p.x, w[c][2*jj]);
                    fma2(a1[c], p.y, w[c][2*jj+1]);
                }
            }
            float s[4];
#pragma unroll
            for (int c = 0; c < 4; c++) {
                const float2 f = unpack2(add2(a0[c], a1[c]));
                s[c] = f.x + f.y;
            }
            // packed 64-bit red writes (contiguous 256B per warp per store)
            *(ull*)&red[wid][r][nc[0]] = pack2(s[0], s[1]);
            *(ull*)&red[wid][r][nc[2]] = pack2(s[2], s[3]);
        }
        __syncthreads();                 // barrier 2: partials ready

        // ---- phase B: pair-split reduce (8 LDS.64 + add2 tree + shfl) ----
        {
            ull v0 = *(const ull*)&red[slb + 0][rrow][pc];
            ull v1 = *(const ull*)&red[slb + 1][rrow][pc];
            ull v2 = *(const ull*)&red[slb + 2][rrow][pc];
            ull v3 = *(const ull*)&red[slb + 3][rrow][pc];
            ull v4 = *(const ull*)&red[slb + 4][rrow][pc];
            ull v5 = *(const ull*)&red[slb + 5][rrow][pc];
            ull v6 = *(const ull*)&red[slb + 6][rrow][pc];
            ull v7 = *(const ull*)&red[slb + 7][rrow][pc];
            ull s = add2(add2(add2(v0, v1), add2(v2, v3)),
                         add2(add2(v4, v5), add2(v6, v7)));
            s = add2(s, shfl_xor64(s, 1));      // combine halves
            if (half == 0) {
                s = add2(s, biasp);
                *(ull*)&cur[wbuf][rrow][pc] = s;
                *(ull*)&g_nodes[((size_t)(b0 + rrow) * NI + j) * EE + pc] = s;
            }
        }
        // next iteration's barrier 1 orders cur[wbuf] commits vs reads
    }
}

// ---------------- parallel projection: op = node @ G_w + G_b ----------------
// 4 nodes per warp (4 outstanding LDG.128 -> DRAM latency shared)
__global__ void __launch_bounds__(256) proj_kernel(
    const float* __restrict__ Gw,   // [E, OPS]
    const float* __restrict__ Gb,   // [OPS]
    float* __restrict__ out,        // [B, NI, OPS]
    int total_quads)
{
    __shared__ float gws[EE * OPS];
    __shared__ float gbs[OPS];
    const int t = threadIdx.x;
    for (int i = t; i < EE * OPS; i += blockDim.x) gws[i] = Gw[i];
    if (t < OPS) gbs[t] = Gb[t];
    __syncthreads();

    const int quad = blockIdx.x * (blockDim.x >> 5) + (t >> 5);
    if (quad >= total_quads) return;
    const int lane  = t & 31;
    const size_t n0 = (size_t)quad * 4;

    float4 x[4];
#pragma unroll
    for (int q = 0; q < 4; q++)
        x[q] = *(const float4*)&g_nodes[(n0 + q) * EE + lane * 4];
    const float* g = &gws[lane * 4 * OPS];

    float p[4][OPS];
#pragma unroll
    for (int q = 0; q < 4; q++)
#pragma unroll
        for (int o = 0; o < OPS; o++)
            p[q][o] = x[q].x * g[o] + x[q].y * g[OPS + o]
                    + x[q].z * g[2 * OPS + o] + x[q].w * g[3 * OPS + o];

#pragma unroll
    for (int off = 16; off; off >>= 1)
#pragma unroll
        for (int q = 0; q < 4; q++)
#pragma unroll
            for (int o = 0; o < OPS; o++)
                p[q][o] += __shfl_xor_sync(0xFFFFFFFFu, p[q][o], off);

    if (lane == 0) {
        float* op = out + n0 * OPS;
#pragma unroll
        for (int q = 0; q < 4; q++)
#pragma unroll
            for (int o = 0; o < OPS; o++)
                op[q * OPS + o] = p[q][o] + gbs[o];
    }
}

// ---------------- labels tail ----------------
// Labels land on device as int32 (JAX x64 disabled). mode 1: float cast.
// mode 2: widen to raw int64.
__global__ void tail_kernel(const int* __restrict__ labels, float* __restrict__ out, int mode)
{
    const int j = blockIdx.x * blockDim.x + threadIdx.x;
    if (j >= NI) return;
    const size_t base = (size_t)BB * NI * OPS;
    if (mode == 1) {
        out[base + j] = (float)labels[j];
    } else {
        ((long long*)(out + base))[j] = (long long)labels[j];
    }
}

extern "C" void kernel_launch(void* const* d_in, const int* in_sizes, int n_in,
                              void* d_out, int out_size)
{
    const float* emb    = (const float*)d_in[0];
    const float* Ww     = (const float*)d_in[1];
    const float* Wb     = (const float*)d_in[2];
    const float* Gw     = (const float*)d_in[3];
    const float* Gb     = (const float*)d_in[4];
    const int*   li     = (const int*)d_in[5];
    const int*   ri     = (const int*)d_in[6];
    const int*   labels = (const int*)d_in[7];
    float*       out    = (float*)d_out;

    recur_kernel<<<BB / RPC, 512>>>(emb, Ww, Wb, li, ri);

    const int total_quads = BB * NI / 4;                   // 65408
    proj_kernel<<<total_quads / 8, 256>>>(Gw, Gb, out, total_quads); // 8 warps/block

    const long long base = (long long)BB * NI * OPS;
    const long long tail = (long long)out_size - base;
    if (tail == NI)          tail_kernel<<<2, 256>>>(labels, out, 1);
    else if (tail == 2 * NI) tail_kernel<<<2, 256>>>(labels, out, 2);
}

// round 14
// speedup vs baseline: 1.5672x; 1.1194x over previous
#include <cuda_runtime.h>
#include <cstdint>

#define BB   512      // batch
#define LL   512      // leaves
#define EE   128      // emb
#define OPS  5
#define NI   511      // internal nodes
#define RPC  4        // batch rows per CTA

typedef unsigned long long ull;

// scratch: all node embeddings [B][NI][E]  (~134 MB)
__device__ float g_nodes[(size_t)BB * NI * EE];

// ---------------- packed f32x2 helpers ----------------
__device__ __forceinline__ ull pack2(float lo, float hi) {
    ull r;
    asm("mov.b64 %0, {%1, %2};" : "=l"(r) : "f"(lo), "f"(hi));
    return r;
}
__device__ __forceinline__ void fma2(ull& d, ull a, ull b) {
    asm("fma.rn.f32x2 %0, %1, %2, %0;" : "+l"(d) : "l"(a), "l"(b));
}
__device__ __forceinline__ ull add2(ull a, ull b) {
    ull r;
    asm("add.rn.f32x2 %0, %1, %2;" : "=l"(r) : "l"(a), "l"(b));
    return r;
}
__device__ __forceinline__ float2 unpack2(ull v) {
    float2 f;
    asm("mov.b64 {%0, %1}, %2;" : "=f"(f.x), "=f"(f.y) : "l"(v));
    return f;
}

// ---------------- sequential recurrence ----------------
// Warp-sliced broadcast layout at 512 threads = 16 warps (4 warps/SMSP).
// Warp w owns the 16-float K-slice [16w..16w+15] of the 256-float concat
// [cur | leaf] (warps 0-7: cur, 8-15: leaf). Lane l owns output cols
// {l, l+32, l+64, l+96}. All 32 lanes read the SAME 16B x-chunk ->
// broadcast = 1 L1 wavefront per LDS.128.
// Per thread-step: 16 LDS.128-bcast + 128 fma2 + 16 STS (phase A) and
// 16 coalesced LDS + depth-4 add tree (phase B). 2 barriers/step.
// Phase-A base pointers hoisted out of the step loop (no per-row selects).
__global__ void __launch_bounds__(512, 1) recur_kernel(
    const float* __restrict__ emb,   // [B, L, E]
    const float* __restrict__ Ww,    // [2E, E]
    const float* __restrict__ Wb,    // [E]
    const int*   __restrict__ li,    // [NI]
    const int*   __restrict__ ri)    // [NI]
{
    __shared__ __align__(16) float cur[2][RPC][EE];    // double-buffered state
    __shared__ __align__(16) float leafs[2][RPC][EE];  // double-buffered right leaf
    __shared__ __align__(16) float red[16][RPC][EE];   // per-warp partials (32 KB)
    __shared__ int ridx[NI + 2];

    const int t    = threadIdx.x;
    const int wid  = t >> 5;        // warp = K-slice 0..15
    const int lane = t & 31;
    const int b0   = blockIdx.x * RPC;

    // Weight slice: Ww rows 16*wid..+15, cols lane+32c. 32 b64 regs.
    ull w[4][8];
#pragma unroll
    for (int c = 0; c < 4; c++) {
        const int n = lane + 32 * c;
#pragma unroll
        for (int i = 0; i < 8; i++) {
            const int k = 16 * wid + 2 * i;
            w[c][i] = pack2(Ww[(size_t)k * EE + n], Ww[(size_t)(k + 1) * EE + n]);
        }
    }
    // reduce-phase ownership: thread commits exactly one (rrow, rcol)
    const int   rcol  = t & 127;
    const int   rrow  = t >> 7;     // 0..3
    const float biasv = Wb[rcol];

    // phase-A x base pointers (hoisted; rb selects between the two)
    // cur[rb][r][wid*16]  == (ull2*)cur  + rb*RPC*32 + r*32 + wid*4
    // leafs[rb][r][s*16]  == (ull2*)leafs+ rb*RPC*32 + r*32 + s*4, s = wid-8
    const ulonglong2* xbase0;
    const ulonglong2* xbase1;
    if (wid < 8) {
        xbase0 = (const ulonglong2*)cur + wid * 4;
        xbase1 = xbase0 + RPC * 32;
    } else {
        xbase0 = (const ulonglong2*)leafs + (wid - 8) * 4;
        xbase1 = xbase0 + RPC * 32;
    }

    // right-leaf indices into smem (+2 dummies for distance-2 prefetch)
    for (int j = t; j < NI; j += 512) ridx[j] = ri[j];
    if (t == 0) { ridx[NI] = ri[0]; ridx[NI + 1] = ri[0]; }

    // init cur[0] = leaf(left_idx[0]); loader: 4 rows x 128 cols, 1 float each
    const int l0   = li[0];
    const int r_ld = t >> 7;
    const int c_ld = t & 127;
    cur[0][r_ld][c_ld] = emb[((size_t)(b0 + r_ld) * LL + l0) * EE + c_ld];
    __syncthreads();

    // distance-2 leaf prefetch
    float lv0 = emb[((size_t)(b0 + r_ld) * LL + ridx[0]) * EE + c_ld];
    float lv1 = emb[((size_t)(b0 + r_ld) * LL + ridx[1]) * EE + c_ld];

    for (int j = 0; j < NI; j++) {
        const int rb   = j & 1;         // read state buffer
        const int wbuf = rb ^ 1;        // write state buffer
        // commit leaf for this step; barrier 1 covers leaf + prev cur commits
        leafs[rb][r_ld][c_ld] = lv0;
        const int rnext = ridx[j + 2];
        __syncthreads();
        lv0 = lv1;
        lv1 = emb[((size_t)(b0 + r_ld) * LL + rnext) * EE + c_ld];

        const ulonglong2* xb = rb ? xbase1 : xbase0;

        // ---- phase A: per-warp 16-K-slice partials, broadcast x reads ----
#pragma unroll
        for (int r = 0; r < RPC; r++) {
            const ulonglong2* xs = xb + r * 32;
            ull a0[4] = {0ull, 0ull, 0ull, 0ull};
            ull a1[4] = {0ull, 0ull, 0ull, 0ull};
#pragma unroll
            for (int jj = 0; jj < 4; jj++) {
                const ulonglong2 p = xs[jj];        // broadcast: 1 wavefront
#pragma unroll
                for (int c = 0; c < 4; c++) {
                    fma2(a0[c], p.x, w[c][2*jj]);
                    fma2(a1[c], p.y, w[c][2*jj+1]);
                }
            }
#pragma unroll
            for (int c = 0; c < 4; c++) {
                const float2 f = unpack2(add2(a0[c], a1[c]));
                red[wid][r][lane + 32 * c] = f.x + f.y;   // contiguous per warp
            }
        }
        __syncthreads();                 // barrier 2: partials ready

        // ---- phase B: batched loads + depth-4 tree, 1 commit per thread ----
        {
            float v[16];
#pragma unroll
            for (int sl = 0; sl < 16; sl++) v[sl] = red[sl][rrow][rcol];
            float s01 = v[0] + v[1],   s23 = v[2] + v[3];
            float s45 = v[4] + v[5],   s67 = v[6] + v[7];
            float s89 = v[8] + v[9],   sab = v[10] + v[11];
            float scd = v[12] + v[13], sef = v[14] + v[15];
            float s = ((s01 + s23) + (s45 + s67)) + ((s89 + sab) + (scd + sef));
            const float vout = s + biasv;
            cur[wbuf][rrow][rcol] = vout;
            g_nodes[((size_t)(b0 + rrow) * NI + j) * EE + rcol] = vout;
        }
        // next iteration's barrier 1 orders cur[wbuf] commits vs reads
    }
}

// ---------------- parallel projection: op = node @ G_w + G_b ----------------
// 4 nodes per warp (4 outstanding LDG.128 -> DRAM latency shared)
__global__ void __launch_bounds__(256) proj_kernel(
    const float* __restrict__ Gw,   // [E, OPS]
    const float* __restrict__ Gb,   // [OPS]
    float* __restrict__ out,        // [B, NI, OPS]
    int total_quads)
{
    __shared__ float gws[EE * OPS];
    __shared__ float gbs[OPS];
    const int t = threadIdx.x;
    for (int i = t; i < EE * OPS; i += blockDim.x) gws[i] = Gw[i];
    if (t < OPS) gbs[t] = Gb[t];
    __syncthreads();

    const int quad = blockIdx.x * (blockDim.x >> 5) + (t >> 5);
    if (quad >= total_quads) return;
    const int lane  = t & 31;
    const size_t n0 = (size_t)quad * 4;

    float4 x[4];
#pragma unroll
    for (int q = 0; q < 4; q++)
        x[q] = *(const float4*)&g_nodes[(n0 + q) * EE + lane * 4];
    const float* g = &gws[lane * 4 * OPS];

    float p[4][OPS];
#pragma unroll
    for (int q = 0; q < 4; q++)
#pragma unroll
        for (int o = 0; o < OPS; o++)
            p[q][o] = x[q].x * g[o] + x[q].y * g[OPS + o]
                    + x[q].z * g[2 * OPS + o] + x[q].w * g[3 * OPS + o];

#pragma unroll
    for (int off = 16; off; off >>= 1)
#pragma unroll
        for (int q = 0; q < 4; q++)
#pragma unroll
            for (int o = 0; o < OPS; o++)
                p[q][o] += __shfl_xor_sync(0xFFFFFFFFu, p[q][o], off);

    if (lane == 0) {
        float* op = out + n0 * OPS;
#pragma unroll
        for (int q = 0; q < 4; q++)
#pragma unroll
            for (int o = 0; o < OPS; o++)
                op[q * OPS + o] = p[q][o] + gbs[o];
    }
}

// ---------------- labels tail ----------------
// Labels land on device as int32 (JAX x64 disabled). mode 1: float cast.
// mode 2: widen to raw int64.
__global__ void tail_kernel(const int* __restrict__ labels, float* __restrict__ out, int mode)
{
    const int j = blockIdx.x * blockDim.x + threadIdx.x;
    if (j >= NI) return;
    const size_t base = (size_t)BB * NI * OPS;
    if (mode == 1) {
        out[base + j] = (float)labels[j];
    } else {
        ((long long*)(out + base))[j] = (long long)labels[j];
    }
}

extern "C" void kernel_launch(void* const* d_in, const int* in_sizes, int n_in,
                              void* d_out, int out_size)
{
    const float* emb    = (const float*)d_in[0];
    const float* Ww     = (const float*)d_in[1];
    const float* Wb     = (const float*)d_in[2];
    const float* Gw     = (const float*)d_in[3];
    const float* Gb     = (const float*)d_in[4];
    const int*   li     = (const int*)d_in[5];
    const int*   ri     = (const int*)d_in[6];
    const int*   labels = (const int*)d_in[7];
    float*       out    = (float*)d_out;

    recur_kernel<<<BB / RPC, 512>>>(emb, Ww, Wb, li, ri);

    const int total_quads = BB * NI / 4;                   // 65408
    proj_kernel<<<total_quads / 8, 256>>>(Gw, Gb, out, total_quads); // 8 warps/block

    const long long base = (long long)BB * NI * OPS;
    const long long tail = (long long)out_size - base;
    if (tail == NI)          tail_kernel<<<2, 256>>>(labels, out, 1);
    else if (tail == 2 * NI) tail_kernel<<<2, 256>>>(labels, out, 2);
}